// round 2
// baseline (speedup 1.0000x reference)
#include <cuda_runtime.h>
#include <cuda_bf16.h>

#define ROWS 4096
#define COLS 32000
#define NF4  (COLS / 4)                  // 8000 float4 per row
#define CAP  3072                        // compacted tail capacity (expected ~730)
#define BD   256                         // block dim
#define NCHUNK ((NF4 + BD - 1) / BD)     // 32 uniform chunks (last partially OOB)
#define NEG_INF (-3.402823466e38f)

// ---------------------------------------------------------------------------
// Single fused kernel: rowmax -> compact tail (L2-hot re-read) -> bisect on
// warp 0 -> zero-fill output + scatter nonzeros. One CTA (256 thr) per row.
// ---------------------------------------------------------------------------
__global__ __launch_bounds__(BD, 8) void entmax_fused_kernel(const float* __restrict__ X,
                                                             float* __restrict__ out) {
    const int row = blockIdx.x;
    const float4* Xr = reinterpret_cast<const float4*>(X + (size_t)row * COLS);
    float4* Or = reinterpret_cast<float4*>(out + (size_t)row * COLS);

    __shared__ float s_vals[CAP];
    __shared__ int   s_idx[CAP];
    __shared__ float s_red[8];
    __shared__ int   s_count;
    __shared__ float s_tau, s_invZ;

    const int tid  = threadIdx.x;
    const int lane = tid & 31;
    const int wrp  = tid >> 5;

    if (tid == 0) s_count = 0;

    // ---- Phase A: row max (streaming HBM read, data lands in L2/L1)
    float m = NEG_INF;
    for (int i = tid; i < NF4; i += BD) {
        float4 v = Xr[i];
        m = fmaxf(m, fmaxf(fmaxf(v.x, v.y), fmaxf(v.z, v.w)));
    }
    #pragma unroll
    for (int o = 16; o > 0; o >>= 1)
        m = fmaxf(m, __shfl_xor_sync(0xFFFFFFFFu, m, o));
    if (lane == 0) s_red[wrp] = m;
    __syncthreads();
    if (wrp == 0) {
        m = (lane < (BD >> 5)) ? s_red[lane] : NEG_INF;
        #pragma unroll
        for (int o = 4; o > 0; o >>= 1)
            m = fmaxf(m, __shfl_xor_sync(0xFFFFFFFFu, m, o));
        if (lane == 0) s_red[0] = m;
    }
    __syncthreads();

    const float max_s  = s_red[0] * 0.5f;   // max_val * (alpha-1), alpha-1 = 0.5 exact
    const float thresh = max_s - 1.0f;      // initial tau_lo; only Xs > thresh can be nonzero

    // ---- Phase B: compaction (re-read is L2/L1 hot; warp-aggregated push)
    #pragma unroll 1
    for (int c = 0; c < NCHUNK; c++) {
        const int i = c * BD + tid;
        float4 v;
        if (i < NF4) v = Xr[i];
        else         v = make_float4(NEG_INF, NEG_INF, NEG_INF, NEG_INF);
        const float xs[4] = {v.x * 0.5f, v.y * 0.5f, v.z * 0.5f, v.w * 0.5f};
        #pragma unroll
        for (int k = 0; k < 4; k++) {
            const bool p = xs[k] > thresh;
            const unsigned mask = __ballot_sync(0xFFFFFFFFu, p);
            if (mask == 0u) continue;
            if (p) {
                const int rank   = __popc(mask & ((1u << lane) - 1u));
                const int leader = __ffs(mask) - 1;
                int base = 0;
                if (lane == leader) base = atomicAdd(&s_count, __popc(mask));
                base = __shfl_sync(mask, base, leader);
                const int idx = base + rank;
                if (idx < CAP) {
                    s_vals[idx] = xs[k];
                    s_idx[idx]  = i * 4 + k;
                }
            }
        }
    }
    __syncthreads();

    const int  cnt = s_count;
    const int  n   = (cnt < CAP) ? cnt : CAP;
    const bool ovf = (cnt > CAP);            // near-impossible for this data; exact fallback

    // ---- Phase C: 50-iter bisection on warp 0 over compacted values
    if (wrp == 0) {
        float tau_lo = max_s - 1.0f;
        const float tau_hi = max_s - 0.005590169943749474f;  // max_s - (1/d)^(alpha-1)
        float dm = tau_hi - tau_lo;
        float tau_m = tau_lo;
        float Z = 1.0f;
        const float* Xrow = X + (size_t)row * COLS;

        #pragma unroll 1
        for (int it = 0; it < 50; it++) {
            dm *= 0.5f;
            tau_m = tau_lo + dm;
            float acc = 0.0f;
            if (!ovf) {
                #pragma unroll 4
                for (int j = lane; j < n; j += 32) {
                    float t = fmaxf(s_vals[j] - tau_m, 0.0f);
                    acc = fmaf(t, t, acc);
                }
            } else {
                for (int j = lane; j < COLS; j += 32) {
                    float t = fmaxf(fmaf(Xrow[j], 0.5f, -tau_m), 0.0f);
                    acc = fmaf(t, t, acc);
                }
            }
            #pragma unroll
            for (int o = 16; o > 0; o >>= 1)
                acc += __shfl_xor_sync(0xFFFFFFFFu, acc, o);
            if (acc - 1.0f >= 0.0f) tau_lo = tau_m;
            Z = acc;   // sum at this iteration's tau_m (matches reference's final p_m)
        }
        if (lane == 0) {
            s_tau  = tau_m;
            s_invZ = 1.0f / Z;
        }
    }
    __syncthreads();

    const float tau  = s_tau;
    const float invZ = s_invZ;

    // ---- Phase D: output. Non-compacted elements are exactly 0 (tau_m > thresh),
    // so zero-fill the row and scatter the <=n nonzero values. No third read of X.
    if (!ovf) {
        const float4 z4 = make_float4(0.0f, 0.0f, 0.0f, 0.0f);
        for (int i = tid; i < NF4; i += BD)
            Or[i] = z4;
        __syncthreads();
        float* Orow = out + (size_t)row * COLS;
        for (int j = tid; j < n; j += BD) {
            const float t = fmaxf(s_vals[j] - tau, 0.0f);
            Orow[s_idx[j]] = t * t * invZ;
        }
    } else {
        for (int i = tid; i < NF4; i += BD) {
            float4 v = Xr[i];
            float4 o; float t;
            t = fmaxf(v.x * 0.5f - tau, 0.0f); o.x = t * t * invZ;
            t = fmaxf(v.y * 0.5f - tau, 0.0f); o.y = t * t * invZ;
            t = fmaxf(v.z * 0.5f - tau, 0.0f); o.z = t * t * invZ;
            t = fmaxf(v.w * 0.5f - tau, 0.0f); o.w = t * t * invZ;
            Or[i] = o;
        }
    }
}

// ---------------------------------------------------------------------------
extern "C" void kernel_launch(void* const* d_in, const int* in_sizes, int n_in,
                              void* d_out, int out_size) {
    const float* X = (const float*)d_in[0];
    float* out = (float*)d_out;
    entmax_fused_kernel<<<ROWS, BD>>>(X, out);
}